// round 5
// baseline (speedup 1.0000x reference)
#include <cuda_runtime.h>
#include <cuda_bf16.h>
#include <math.h>
#include <stdint.h>

#define E_     8
#define B_     4096
#define D_IN_  1024
#define D_HID_ 2048
#define D_OUT_ 1024
#define G_HID_ 128
#define K_     2

// ==================== helpers ====================
__device__ __forceinline__ uint32_t smem_u32(const void* p) {
    uint32_t a;
    asm("{ .reg .u64 t; cvta.to.shared.u64 t, %1; cvt.u32.u64 %0, t; }" : "=r"(a) : "l"(p));
    return a;
}
__device__ __forceinline__ uint32_t swz64(uint32_t off) { return off ^ ((off >> 3) & 0x30); }

__device__ __forceinline__ void split2(float a, float b, uint32_t& hi, uint32_t& lo) {
    __nv_bfloat16 ha = __float2bfloat16_rn(a), hb = __float2bfloat16_rn(b);
    float ra = a - __bfloat162float(ha);
    float rb = b - __bfloat162float(hb);
    __nv_bfloat16 la = __float2bfloat16_rn(ra), lb = __float2bfloat16_rn(rb);
    hi = (uint32_t)__bfloat16_as_ushort(ha) | ((uint32_t)__bfloat16_as_ushort(hb) << 16);
    lo = (uint32_t)__bfloat16_as_ushort(la) | ((uint32_t)__bfloat16_as_ushort(lb) << 16);
}

#define LDM4(r, addr) \
    asm volatile("ldmatrix.sync.aligned.m8n8.x4.shared.b16 {%0,%1,%2,%3}, [%4];" \
        : "=r"((r)[0]), "=r"((r)[1]), "=r"((r)[2]), "=r"((r)[3]) : "r"(addr))

#define MMA_BF16(c, a, b0, b1) \
    asm volatile("mma.sync.aligned.m16n8k16.row.col.f32.bf16.bf16.f32 " \
        "{%0,%1,%2,%3},{%4,%5,%6,%7},{%8,%9},{%0,%1,%2,%3};" \
        : "+f"((c)[0]), "+f"((c)[1]), "+f"((c)[2]), "+f"((c)[3]) \
        : "r"((a)[0]), "r"((a)[1]), "r"((a)[2]), "r"((a)[3]), "r"(b0), "r"(b1))

#define CP_ASYNC16(dst, src) \
    asm volatile("cp.async.cg.shared.global [%0], [%1], 16;" :: "r"(dst), "l"(src) : "memory")
#define CP_COMMIT() asm volatile("cp.async.commit_group;" ::: "memory")
#define CP_WAIT1()  asm volatile("cp.async.wait_group 1;" ::: "memory")
#define CP_WAIT0()  asm volatile("cp.async.wait_group 0;" ::: "memory")

// ==================== device scratch ====================
__device__ int   g_counts[E_];
__device__ int   g_offsets[E_];
__device__ int   g_cursor[E_];
__device__ int   g_tok_e[B_ * K_];
__device__ float g_tok_s[B_ * K_];
__device__ int   g_tok_pos[B_ * K_];
__device__ int   g_pair_token[B_ * K_];
__device__ float g_entropy[B_];
__device__ int   g_bad;

__device__ __align__(16) __nv_bfloat16 g_x_hi[(size_t)B_ * D_IN_];
__device__ __align__(16) __nv_bfloat16 g_x_lo[(size_t)B_ * D_IN_];
__device__ __align__(16) __nv_bfloat16 g_w1t_hi[(size_t)E_ * D_HID_ * D_IN_];
__device__ __align__(16) __nv_bfloat16 g_w1t_lo[(size_t)E_ * D_HID_ * D_IN_];
__device__ __align__(16) __nv_bfloat16 g_w2t_hi[(size_t)E_ * D_HID_ * D_HID_];
__device__ __align__(16) __nv_bfloat16 g_w2t_lo[(size_t)E_ * D_HID_ * D_HID_];
__device__ __align__(16) __nv_bfloat16 g_w3t_hi[(size_t)E_ * D_OUT_ * D_HID_];
__device__ __align__(16) __nv_bfloat16 g_w3t_lo[(size_t)E_ * D_OUT_ * D_HID_];
__device__ __align__(16) __nv_bfloat16 g_h1_hi[(size_t)B_ * K_ * D_HID_];
__device__ __align__(16) __nv_bfloat16 g_h1_lo[(size_t)B_ * K_ * D_HID_];
__device__ __align__(16) __nv_bfloat16 g_h2_hi[(size_t)B_ * K_ * D_HID_];
__device__ __align__(16) __nv_bfloat16 g_h2_lo[(size_t)B_ * K_ * D_HID_];
__device__ __align__(16) float g_o_pair[(size_t)B_ * K_ * D_OUT_];
// fp32 fallback scratch
__device__ __align__(16) float g_f1[(size_t)B_ * K_ * D_HID_];
__device__ __align__(16) float g_f2[(size_t)B_ * K_ * D_HID_];

// ==================== small kernels ====================
__global__ void init_kernel() {
    if (threadIdx.x < E_) { g_counts[threadIdx.x] = 0; g_cursor[threadIdx.x] = 0; }
    if (threadIdx.x == 0) g_bad = 0;
}

__global__ __launch_bounds__(256)
void prep_x(const float* __restrict__ x) {
    int i = blockIdx.x * 256 + threadIdx.x;
    float v = x[i];
    __nv_bfloat16 h = __float2bfloat16_rn(v);
    g_x_hi[i] = h;
    g_x_lo[i] = __float2bfloat16_rn(v - __bfloat162float(h));
}

__global__ __launch_bounds__(256)
void prep_w(const float* __restrict__ W, __nv_bfloat16* __restrict__ Whi,
            __nv_bfloat16* __restrict__ Wlo, int KD, int ND)
{
    __shared__ float t[32][33];
    const int e = blockIdx.z;
    const float* Wb = W + (size_t)e * KD * ND;
    __nv_bfloat16* Hh = Whi + (size_t)e * KD * ND;
    __nv_bfloat16* Hl = Wlo + (size_t)e * KD * ND;
    const int n0 = blockIdx.x * 32, k0 = blockIdx.y * 32;
    const int tx = threadIdx.x, ty = threadIdx.y;
    #pragma unroll
    for (int i = 0; i < 4; i++) {
        int kl = ty + i * 8;
        t[kl][tx] = Wb[(size_t)(k0 + kl) * ND + n0 + tx];
    }
    __syncthreads();
    #pragma unroll
    for (int i = 0; i < 4; i++) {
        int nl = ty + i * 8;
        float v = t[tx][nl];
        __nv_bfloat16 h = __float2bfloat16_rn(v);
        __nv_bfloat16 l = __float2bfloat16_rn(v - __bfloat162float(h));
        size_t o = (size_t)(n0 + nl) * KD + k0 + tx;
        Hh[o] = h; Hl[o] = l;
    }
}

__global__ __launch_bounds__(128)
void gate_kernel(const float* __restrict__ x,
                 const float* __restrict__ Wg1, const float* __restrict__ bg1,
                 const float* __restrict__ Wg2, const float* __restrict__ bg2,
                 const float* __restrict__ Wg3, const float* __restrict__ bg3,
                 float* __restrict__ out, long long out_sz)
{
    __shared__ __align__(16) float xs[8][D_IN_];
    __shared__ float s_g1[8][G_HID_];
    __shared__ float s_g2[8][G_HID_];
    __shared__ float s_lg[8][E_];

    const int tid = threadIdx.x;
    const int t0  = blockIdx.x * 8;

    const float4* xg  = reinterpret_cast<const float4*>(x + (size_t)t0 * D_IN_);
    float4*       xsv = reinterpret_cast<float4*>(&xs[0][0]);
    #pragma unroll
    for (int i = 0; i < (8 * D_IN_ / 4) / 128; i++)
        xsv[tid + i * 128] = xg[tid + i * 128];
    __syncthreads();

    float acc[8];
    #pragma unroll
    for (int t = 0; t < 8; t++) acc[t] = 0.f;
    for (int i = 0; i < D_IN_; i++) {
        float w = Wg1[i * G_HID_ + tid];
        #pragma unroll
        for (int t = 0; t < 8; t++) acc[t] = fmaf(xs[t][i], w, acc[t]);
    }
    {
        float b = bg1[tid];
        #pragma unroll
        for (int t = 0; t < 8; t++) s_g1[t][tid] = fmaxf(acc[t] + b, 0.f);
    }
    __syncthreads();

    #pragma unroll
    for (int t = 0; t < 8; t++) acc[t] = 0.f;
    for (int i = 0; i < G_HID_; i++) {
        float w = Wg2[i * G_HID_ + tid];
        #pragma unroll
        for (int t = 0; t < 8; t++) acc[t] = fmaf(s_g1[t][i], w, acc[t]);
    }
    {
        float b = bg2[tid];
        #pragma unroll
        for (int t = 0; t < 8; t++) s_g2[t][tid] = fmaxf(acc[t] + b, 0.f);
    }
    __syncthreads();

    if (tid < 64) {
        int t = tid >> 3, e = tid & 7;
        float a = bg3[e];
        for (int i = 0; i < G_HID_; i++)
            a = fmaf(s_g2[t][i], Wg3[i * E_ + e], a);
        s_lg[t][e] = a;
    }
    __syncthreads();

    if (tid < 8) {
        const int t   = tid;
        const int tok = t0 + t;
        float p[E_];
        float mx = s_lg[t][0];
        #pragma unroll
        for (int e = 1; e < E_; e++) mx = fmaxf(mx, s_lg[t][e]);
        float s = 0.f;
        #pragma unroll
        for (int e = 0; e < E_; e++) { p[e] = expf(s_lg[t][e] - mx); s += p[e]; }
        float inv = 1.f / s;
        float ent = 0.f;
        #pragma unroll
        for (int e = 0; e < E_; e++) { p[e] *= inv; ent -= p[e] * logf(p[e] + 1e-9f); }
        g_entropy[tok] = ent;

        int i1 = 0;
        #pragma unroll
        for (int e = 1; e < E_; e++) if (p[e] > p[i1]) i1 = e;
        int i2 = (i1 == 0) ? 1 : 0;
        #pragma unroll
        for (int e = 0; e < E_; e++) if (e != i1 && p[e] > p[i2]) i2 = e;

        float s1 = p[i1], s2 = p[i2];
        atomicAdd(&g_counts[i1], 1);
        atomicAdd(&g_counts[i2], 1);
        float denom = s1 + s2 + 1e-9f;
        g_tok_e[tok * 2 + 0] = i1;
        g_tok_e[tok * 2 + 1] = i2;
        g_tok_s[tok * 2 + 0] = s1 / denom;
        g_tok_s[tok * 2 + 1] = s2 / denom;

        long long idx_off = (long long)B_ * D_OUT_ + 1;
        long long sc_off  = idx_off + (long long)B_ * K_;
        if (out_sz >= sc_off + (long long)B_ * K_) {
            out[idx_off + tok * 2 + 0] = (float)i1;
            out[idx_off + tok * 2 + 1] = (float)i2;
            out[sc_off  + tok * 2 + 0] = s1;
            out[sc_off  + tok * 2 + 1] = s2;
        }
    }
}

__global__ void offsets_kernel() {
    if (threadIdx.x == 0 && blockIdx.x == 0) {
        int off = 0;
        for (int e = 0; e < E_; e++) {
            g_offsets[e] = off;
            g_cursor[e]  = off;
            off += g_counts[e];
        }
    }
}

__global__ void scatter_kernel() {
    int tok = blockIdx.x * blockDim.x + threadIdx.x;
    if (tok >= B_) return;
    #pragma unroll
    for (int k = 0; k < K_; k++) {
        int e = g_tok_e[tok * 2 + k];
        int pos = atomicAdd(&g_cursor[e], 1);
        g_pair_token[pos] = tok;
        g_tok_pos[tok * 2 + k] = pos;
    }
}

// ==================== HMMA expert GEMM (fast path) ====================
#define KC       32
#define STG      24576
#define T_AHI    0
#define T_ALO    8192
#define T_BHI    16384
#define T_BLO    20480
#define GSMEM    (2 * STG)

template<int KDIM, int NDIM, int LAYER>
__global__ __launch_bounds__(256, 1)
void moe_gemm(const float* __restrict__ bstack)
{
    const int e   = blockIdx.z;
    const int cnt = g_counts[e];
    const int m0  = blockIdx.x * 128;
    if (m0 >= cnt) return;
    const int off = g_offsets[e];
    const int n0  = blockIdx.y * 64;

    extern __shared__ char dsm[];
    const uint32_t sb = smem_u32(dsm);
    const int tid = threadIdx.x;

    const __nv_bfloat16* rpa_h = nullptr;
    const __nv_bfloat16* rpa_l = nullptr;
    const __nv_bfloat16* rpb   = nullptr;
    {
        const __nv_bfloat16* Ah = (LAYER == 1) ? g_x_hi : (LAYER == 2 ? g_h1_hi : g_h2_hi);
        const __nv_bfloat16* Al = (LAYER == 1) ? g_x_lo : (LAYER == 2 ? g_h1_lo : g_h2_lo);
        const __nv_bfloat16* Wh = (LAYER == 1) ? g_w1t_hi : (LAYER == 2 ? g_w2t_hi : g_w3t_hi);
        const __nv_bfloat16* Wl = (LAYER == 1) ? g_w1t_lo : (LAYER == 2 ? g_w2t_lo : g_w3t_lo);
        if (tid < 128) {
            const int u = tid;
            int r = m0 + u; if (r >= cnt) r = cnt - 1;
            size_t i0 = (LAYER == 1) ? (size_t)g_pair_token[off + r] * KDIM
                                     : (size_t)(off + r) * KDIM;
            rpa_h = Ah + i0;
            rpa_l = Al + i0;
        } else {
            const int u = tid & 63;
            const __nv_bfloat16* base = (tid < 192) ? Wh : Wl;
            rpb = base + (size_t)e * NDIM * KDIM + (size_t)(n0 + u) * KDIM;
        }
    }

    auto load_stage = [&](int t, int buf) {
        const uint32_t stage = sb + buf * STG;
        const int k0 = t * KC;
        if (tid < 128) {
            const int u = tid;
            #pragma unroll
            for (int c = 0; c < 4; c++) {
                uint32_t o = swz64(u * 64 + c * 16);
                CP_ASYNC16(stage + T_AHI + o, rpa_h + k0 + c * 8);
                CP_ASYNC16(stage + T_ALO + o, rpa_l + k0 + c * 8);
            }
        } else {
            const int u = tid & 63;
            const uint32_t tb = (tid < 192) ? T_BHI : T_BLO;
            #pragma unroll
            for (int c = 0; c < 4; c++) {
                uint32_t o = swz64(u * 64 + c * 16);
                CP_ASYNC16(stage + tb + o, rpb + k0 + c * 8);
            }
        }
    };

    const int wid = tid >> 5, lane = tid & 31;
    const int warp_m0 = (wid & 3) * 32;
    const int warp_n0 = (wid >> 2) * 32;

    const int a_row = lane & 15;
    const int a_chi = ((lane >> 4) << 4);
    const int b_row = (lane & 7) + ((lane >> 4) << 3);
    const int b_chi = (((lane >> 3) & 1) << 4);

    float acc[2][4][4];
    #pragma unroll
    for (int i = 0; i < 2; i++)
        #pragma unroll
        for (int j = 0; j < 4; j++)
            #pragma unroll
            for (int k = 0; k < 4; k++) acc[i][j][k] = 0.f;

    constexpr int NT = KDIM / KC;
    load_stage(0, 0); CP_COMMIT();

    for (int t = 0; t < NT; t++) {
        __syncthreads();
        if (t + 1 < NT) { load_stage(t + 1, (t + 1) & 1); CP_COMMIT(); CP_WAIT1(); }
        else            { CP_WAIT0(); }
        __syncthreads();

        const uint32_t sA = sb + (t & 1) * STG;
        #pragma unroll
        for (int kk = 0; kk < 2; kk++) {
            uint32_t ah[2][4], al[2][4], bh[2][4], bl[2][4];
            #pragma unroll
            for (int mt = 0; mt < 2; mt++) {
                uint32_t o = swz64((warp_m0 + mt * 16 + a_row) * 64 + kk * 32 + a_chi);
                LDM4(ah[mt], sA + T_AHI + o);
                LDM4(al[mt], sA + T_ALO + o);
            }
            #pragma unroll
            for (int np = 0; np < 2; np++) {
                uint32_t o = swz64((warp_n0 + np * 16 + b_row) * 64 + kk * 32 + b_chi);
                LDM4(bh[np], sA + T_BHI + o);
                LDM4(bl[np], sA + T_BLO + o);
            }
            #pragma unroll
            for (int mt = 0; mt < 2; mt++)
                #pragma unroll
                for (int np = 0; np < 2; np++) {
                    MMA_BF16(acc[mt][np * 2],     ah[mt], bh[np][0], bh[np][1]);
                    MMA_BF16(acc[mt][np * 2],     ah[mt], bl[np][0], bl[np][1]);
                    MMA_BF16(acc[mt][np * 2],     al[mt], bh[np][0], bh[np][1]);
                    MMA_BF16(acc[mt][np * 2 + 1], ah[mt], bh[np][2], bh[np][3]);
                    MMA_BF16(acc[mt][np * 2 + 1], ah[mt], bl[np][2], bl[np][3]);
                    MMA_BF16(acc[mt][np * 2 + 1], al[mt], bh[np][2], bh[np][3]);
                }
        }
    }

    const int gid = lane >> 2, tig = lane & 3;
    __nv_bfloat16* Hh = (LAYER == 1) ? g_h1_hi : g_h2_hi;
    __nv_bfloat16* Hl = (LAYER == 1) ? g_h1_lo : g_h2_lo;

    #pragma unroll
    for (int mt = 0; mt < 2; mt++) {
        #pragma unroll
        for (int half = 0; half < 2; half++) {
            const int mr = m0 + warp_m0 + mt * 16 + gid + half * 8;
            if (mr >= cnt) continue;
            const size_t prow = (size_t)(off + mr);
            #pragma unroll
            for (int nt = 0; nt < 4; nt++) {
                const int col = n0 + warp_n0 + nt * 8 + tig * 2;
                float v0 = acc[mt][nt][half * 2 + 0] + bstack[(size_t)e * NDIM + col];
                float v1 = acc[mt][nt][half * 2 + 1] + bstack[(size_t)e * NDIM + col + 1];
                if (LAYER < 3) {
                    v0 = fmaxf(v0, 0.f);
                    v1 = fmaxf(v1, 0.f);
                    uint32_t hi, lo;
                    split2(v0, v1, hi, lo);
                    *reinterpret_cast<uint32_t*>(Hh + prow * NDIM + col) = hi;
                    *reinterpret_cast<uint32_t*>(Hl + prow * NDIM + col) = lo;
                } else {
                    float2 st; st.x = v0; st.y = v1;
                    *reinterpret_cast<float2*>(g_o_pair + prow * D_OUT_ + col) = st;
                }
            }
        }
    }
}

// ==================== verify: fp32 spot-check of HMMA chain ====================
__global__ __launch_bounds__(256)
void verify_kernel(const float* __restrict__ x,
                   const float* __restrict__ We1, const float* __restrict__ be1,
                   const float* __restrict__ We2, const float* __restrict__ be2,
                   const float* __restrict__ We3, const float* __restrict__ be3)
{
    __shared__ float a_in[D_HID_];
    __shared__ int s_bad;
    const int tid = threadIdx.x;
    if (tid == 0) s_bad = 0;
    __syncthreads();

    for (int rc = 0; rc < 2; rc++) {
        const int r = (rc == 0) ? 0 : 101;
        int e = 0;
        for (int i = 0; i < E_; i++)
            if (g_offsets[i] <= r && r < g_offsets[i] + g_counts[i]) e = i;
        const int tok = g_pair_token[r];

        // layer 1 (cols 0..255): x[tok] @ We1[e]
        for (int i = tid; i < D_IN_; i += 256) a_in[i] = x[(size_t)tok * D_IN_ + i];
        __syncthreads();
        {
            const int j = tid;
            float s = be1[(size_t)e * D_HID_ + j];
            const float* w = We1 + (size_t)e * D_IN_ * D_HID_ + j;
            for (int k = 0; k < D_IN_; k++) s = fmaf(a_in[k], w[(size_t)k * D_HID_], s);
            s = fmaxf(s, 0.f);
            float got = __bfloat162float(g_h1_hi[(size_t)r * D_HID_ + j])
                      + __bfloat162float(g_h1_lo[(size_t)r * D_HID_ + j]);
            if (!(fabsf(got - s) <= 5e-3f * (fabsf(s) + 0.1f))) s_bad = 1;
        }
        __syncthreads();

        // layer 2 input = stored h1 row r
        for (int i = tid; i < D_HID_; i += 256)
            a_in[i] = __bfloat162float(g_h1_hi[(size_t)r * D_HID_ + i])
                    + __bfloat162float(g_h1_lo[(size_t)r * D_HID_ + i]);
        __syncthreads();
        {
            const int j = tid;
            float s = be2[(size_t)e * D_HID_ + j];
            const float* w = We2 + (size_t)e * D_HID_ * D_HID_ + j;
            for (int k = 0; k < D_HID_; k++) s = fmaf(a_in[k], w[(size_t)k * D_HID_], s);
            s = fmaxf(s, 0.f);
            float got = __bfloat162float(g_h2_hi[(size_t)r * D_HID_ + j])
                      + __bfloat162float(g_h2_lo[(size_t)r * D_HID_ + j]);
            if (!(fabsf(got - s) <= 5e-3f * (fabsf(s) + 0.1f))) s_bad = 1;
        }
        __syncthreads();

        // layer 3 input = stored h2 row r
        for (int i = tid; i < D_HID_; i += 256)
            a_in[i] = __bfloat162float(g_h2_hi[(size_t)r * D_HID_ + i])
                    + __bfloat162float(g_h2_lo[(size_t)r * D_HID_ + i]);
        __syncthreads();
        {
            const int j = tid;
            float s = be3[(size_t)e * D_OUT_ + j];
            const float* w = We3 + (size_t)e * D_HID_ * D_OUT_ + j;
            for (int k = 0; k < D_HID_; k++) s = fmaf(a_in[k], w[(size_t)k * D_OUT_], s);
            float got = g_o_pair[(size_t)r * D_OUT_ + j];
            if (!(fabsf(got - s) <= 5e-3f * (fabsf(s) + 0.1f))) s_bad = 1;
        }
        __syncthreads();
    }
    if (tid == 0) g_bad = s_bad;
}

// ==================== fp32 fallback GEMM (round-1 proven; runs only if g_bad) ====
#define BM 128
#define BN 128
#define BK 8

// ASRC: 0 = gather x rows by pair token, 1 = g_f1, 2 = g_f2
// EPI : 0 = relu(dot+bias) -> pair-space fp32; 2 = (dot+bias) -> g_o_pair
template<int KDIM, int NDIM, int EPI, int ASRC>
__global__ __launch_bounds__(256, 2)
void fb_gemm(const float* __restrict__ xptr,
             const float* __restrict__ Wstack,
             const float* __restrict__ bstack)
{
    if (g_bad == 0) return;

    const int e   = blockIdx.z;
    const int cnt = g_counts[e];
    const int m0  = blockIdx.y * BM;
    if (m0 >= cnt) return;
    const int off = g_offsets[e];
    const int n0  = blockIdx.x * BN;

    const float* __restrict__ Wb = Wstack + (size_t)e * KDIM * NDIM;
    const float* __restrict__ Abase =
        (ASRC == 0) ? xptr : (ASRC == 1 ? (const float*)g_f1 : (const float*)g_f2);
    float* __restrict__ Obase =
        (EPI == 0) ? (ASRC == 0 ? (float*)g_f1 : (float*)g_f2) : (float*)g_o_pair;

    __shared__ __align__(16) float As[2][BK][BM];
    __shared__ __align__(16) float Bs[2][BK][BN];

    const int tid   = threadIdx.x;
    const int a_row = tid >> 1;
    const int a_kq  = (tid & 1) << 2;
    const int b_k   = tid >> 5;
    const int b_n   = (tid & 31) << 2;

    int m  = m0 + a_row;
    int mm = (m < cnt) ? m : (cnt - 1);
    const float* __restrict__ Arow =
        (ASRC == 0) ? Abase + (size_t)g_pair_token[off + mm] * KDIM
                    : Abase + (size_t)(off + mm) * KDIM;

    const int tx = tid & 15;
    const int ty = tid >> 4;

    float acc[8][8];
    #pragma unroll
    for (int i = 0; i < 8; i++)
        #pragma unroll
        for (int j = 0; j < 8; j++) acc[i][j] = 0.f;

    {
        float4 av = *reinterpret_cast<const float4*>(Arow + a_kq);
        float4 bv = *reinterpret_cast<const float4*>(Wb + (size_t)b_k * NDIM + n0 + b_n);
        As[0][a_kq + 0][a_row] = av.x;
        As[0][a_kq + 1][a_row] = av.y;
        As[0][a_kq + 2][a_row] = av.z;
        As[0][a_kq + 3][a_row] = av.w;
        *reinterpret_cast<float4*>(&Bs[0][b_k][b_n]) = bv;
    }
    __syncthreads();

    const int ntiles = KDIM / BK;
    for (int t = 0; t < ntiles; ++t) {
        const int cur = t & 1;
        const int nxt = cur ^ 1;
        float4 an, bn;
        if (t + 1 < ntiles) {
            const int k0 = (t + 1) * BK;
            an = *reinterpret_cast<const float4*>(Arow + k0 + a_kq);
            bn = *reinterpret_cast<const float4*>(Wb + (size_t)(k0 + b_k) * NDIM + n0 + b_n);
        }
        #pragma unroll
        for (int kk = 0; kk < BK; kk++) {
            float ar[8], br[8];
            *reinterpret_cast<float4*>(&ar[0]) = *reinterpret_cast<const float4*>(&As[cur][kk][ty * 8]);
            *reinterpret_cast<float4*>(&ar[4]) = *reinterpret_cast<const float4*>(&As[cur][kk][ty * 8 + 4]);
            *reinterpret_cast<float4*>(&br[0]) = *reinterpret_cast<const float4*>(&Bs[cur][kk][tx * 8]);
            *reinterpret_cast<float4*>(&br[4]) = *reinterpret_cast<const float4*>(&Bs[cur][kk][tx * 8 + 4]);
            #pragma unroll
            for (int i = 0; i < 8; i++)
                #pragma unroll
                for (int j = 0; j < 8; j++)
                    acc[i][j] = fmaf(ar[i], br[j], acc[i][j]);
        }
        if (t + 1 < ntiles) {
            As[nxt][a_kq + 0][a_row] = an.x;
            As[nxt][a_kq + 1][a_row] = an.y;
            As[nxt][a_kq + 2][a_row] = an.z;
            As[nxt][a_kq + 3][a_row] = an.w;
            *reinterpret_cast<float4*>(&Bs[nxt][b_k][b_n]) = bn;
        }
        __syncthreads();
    }

    const int col0 = n0 + tx * 8;
    float bias[8];
    #pragma unroll
    for (int j = 0; j < 8; j++) bias[j] = bstack[(size_t)e * NDIM + col0 + j];

    #pragma unroll
    for (int i = 0; i < 8; i++) {
        int mr = m0 + ty * 8 + i;
        if (mr >= cnt) continue;
        float* orow = Obase + (size_t)(off + mr) * NDIM + col0;
        #pragma unroll
        for (int j = 0; j < 8; j++) {
            float v = acc[i][j] + bias[j];
            orow[j] = (EPI == 0) ? fmaxf(v, 0.f) : v;
        }
    }
}

// ==================== combine + finalize ====================
__global__ __launch_bounds__(256)
void combine_kernel(float* __restrict__ out)
{
    int i = blockIdx.x * 256 + threadIdx.x;
    int tok = i >> 10, c = i & 1023;
    float v = g_tok_s[tok * 2 + 0] * g_o_pair[(size_t)g_tok_pos[tok * 2 + 0] * D_OUT_ + c]
            + g_tok_s[tok * 2 + 1] * g_o_pair[(size_t)g_tok_pos[tok * 2 + 1] * D_OUT_ + c];
    out[i] = v;
}

__global__ __launch_bounds__(1024)
void finalize_kernel(float* __restrict__ out, long long out_sz)
{
    __shared__ float red[1024];
    const int tid = threadIdx.x;
    float s = 0.f;
    for (int i = tid; i < B_; i += 1024) s += g_entropy[i];
    red[tid] = s;
    __syncthreads();
    for (int st = 512; st > 0; st >>= 1) {
        if (tid < st) red[tid] += red[tid + st];
        __syncthreads();
    }
    if (tid == 0) {
        float ent_mean = red[0] / (float)B_;
        float load[E_];
        float mean = 0.f;
        for (int e = 0; e < E_; e++) {
            load[e] = (float)g_counts[e] / ((float)B_ + 1e-9f);
            mean += load[e];
        }
        mean /= (float)E_;
        float var = 0.f;
        for (int e = 0; e < E_; e++) {
            float d = load[e] - mean;
            var += d * d;
        }
        var /= (float)(E_ - 1);
        float aux = 5.0f * var + 0.1f * ent_mean;
        long long aux_off = (long long)B_ * D_OUT_;
        if (out_sz > aux_off) out[aux_off] = aux;
    }
}

// ==================== launch ====================
extern "C" void kernel_launch(void* const* d_in, const int* in_sizes, int n_in,
                              void* d_out, int out_size)
{
    const float* x   = (const float*)d_in[0];
    const float* We1 = (const float*)d_in[1];
    const float* be1 = (const float*)d_in[2];
    const float* We2 = (const float*)d_in[3];
    const float* be2 = (const float*)d_in[4];
    const float* We3 = (const float*)d_in[5];
    const float* be3 = (const float*)d_in[6];
    const float* Wg1 = (const float*)d_in[7];
    const float* bg1 = (const float*)d_in[8];
    const float* Wg2 = (const float*)d_in[9];
    const float* bg2 = (const float*)d_in[10];
    const float* Wg3 = (const float*)d_in[11];
    const float* bg3 = (const float*)d_in[12];
    float* out = (float*)d_out;
    long long out_sz = (long long)out_size;

    init_kernel<<<1, 32>>>();
    gate_kernel<<<B_ / 8, 128>>>(x, Wg1, bg1, Wg2, bg2, Wg3, bg3, out, out_sz);
    offsets_kernel<<<1, 32>>>();
    scatter_kernel<<<(B_ + 255) / 256, 256>>>();

    prep_x<<<(B_ * D_IN_) / 256, 256>>>(x);
    prep_w<<<dim3(D_HID_ / 32, D_IN_  / 32, E_), dim3(32, 8)>>>(We1, g_w1t_hi, g_w1t_lo, D_IN_,  D_HID_);
    prep_w<<<dim3(D_HID_ / 32, D_HID_ / 32, E_), dim3(32, 8)>>>(We2, g_w2t_hi, g_w2t_lo, D_HID_, D_HID_);
    prep_w<<<dim3(D_OUT_ / 32, D_HID_ / 32, E_), dim3(32, 8)>>>(We3, g_w3t_hi, g_w3t_lo, D_HID_, D_OUT_);

    const int max_mt = B_ / 128;
    moe_gemm<D_IN_,  D_HID_, 1><<<dim3(max_mt, D_HID_ / 64, E_), 256, GSMEM>>>(be1);
    moe_gemm<D_HID_, D_HID_, 2><<<dim3(max_mt, D_HID_ / 64, E_), 256, GSMEM>>>(be2);
    moe_gemm<D_HID_, D_OUT_, 3><<<dim3(max_mt, D_OUT_ / 64, E_), 256, GSMEM>>>(be3);

    verify_kernel<<<1, 256>>>(x, We1, be1, We2, be2, We3, be3);

    fb_gemm<D_IN_,  D_HID_, 0, 0><<<dim3(D_HID_ / BN, max_mt, E_), 256>>>(x, We1, be1);
    fb_gemm<D_HID_, D_HID_, 0, 1><<<dim3(D_HID_ / BN, max_mt, E_), 256>>>(x, We2, be2);
    fb_gemm<D_HID_, D_OUT_, 2, 2><<<dim3(D_OUT_ / BN, max_mt, E_), 256>>>(x, We3, be3);

    combine_kernel<<<(B_ * D_OUT_) / 256, 256>>>(out);
    finalize_kernel<<<1, 1024>>>(out, out_sz);
}

// round 6
// speedup vs baseline: 1.0451x; 1.0451x over previous
#include <cuda_runtime.h>
#include <cuda_bf16.h>
#include <math.h>
#include <stdint.h>

#define E_     8
#define B_     4096
#define D_IN_  1024
#define D_HID_ 2048
#define D_OUT_ 1024
#define G_HID_ 128
#define K_     2

// ==================== helpers ====================
__device__ __forceinline__ void split2(float a, float b, uint32_t& hi, uint32_t& lo) {
    __nv_bfloat16 ha = __float2bfloat16_rn(a), hb = __float2bfloat16_rn(b);
    float ra = a - __bfloat162float(ha);
    float rb = b - __bfloat162float(hb);
    __nv_bfloat16 la = __float2bfloat16_rn(ra), lb = __float2bfloat16_rn(rb);
    hi = (uint32_t)__bfloat16_as_ushort(ha) | ((uint32_t)__bfloat16_as_ushort(hb) << 16);
    lo = (uint32_t)__bfloat16_as_ushort(la) | ((uint32_t)__bfloat16_as_ushort(lb) << 16);
}

#define MMA_BF16(c, a0, a1, a2, a3, b0, b1) \
    asm volatile("mma.sync.aligned.m16n8k16.row.col.f32.bf16.bf16.f32 " \
        "{%0,%1,%2,%3},{%4,%5,%6,%7},{%8,%9},{%0,%1,%2,%3};" \
        : "+f"((c)[0]), "+f"((c)[1]), "+f"((c)[2]), "+f"((c)[3]) \
        : "r"(a0), "r"(a1), "r"(a2), "r"(a3), "r"(b0), "r"(b1))

// ==================== device scratch ====================
__device__ int   g_counts[E_];
__device__ int   g_offsets[E_];
__device__ int   g_cursor[E_];
__device__ int   g_tok_e[B_ * K_];
__device__ float g_tok_s[B_ * K_];
__device__ int   g_tok_pos[B_ * K_];
__device__ int   g_pair_token[B_ * K_];
__device__ float g_entropy[B_];
__device__ int   g_bad;

__device__ __align__(16) __nv_bfloat16 g_x_hi[(size_t)B_ * D_IN_];
__device__ __align__(16) __nv_bfloat16 g_x_lo[(size_t)B_ * D_IN_];
__device__ __align__(16) __nv_bfloat16 g_w1t_hi[(size_t)E_ * D_HID_ * D_IN_];
__device__ __align__(16) __nv_bfloat16 g_w1t_lo[(size_t)E_ * D_HID_ * D_IN_];
__device__ __align__(16) __nv_bfloat16 g_w2t_hi[(size_t)E_ * D_HID_ * D_HID_];
__device__ __align__(16) __nv_bfloat16 g_w2t_lo[(size_t)E_ * D_HID_ * D_HID_];
__device__ __align__(16) __nv_bfloat16 g_w3t_hi[(size_t)E_ * D_OUT_ * D_HID_];
__device__ __align__(16) __nv_bfloat16 g_w3t_lo[(size_t)E_ * D_OUT_ * D_HID_];
__device__ __align__(16) __nv_bfloat16 g_h1_hi[(size_t)B_ * K_ * D_HID_];
__device__ __align__(16) __nv_bfloat16 g_h1_lo[(size_t)B_ * K_ * D_HID_];
__device__ __align__(16) __nv_bfloat16 g_h2_hi[(size_t)B_ * K_ * D_HID_];
__device__ __align__(16) __nv_bfloat16 g_h2_lo[(size_t)B_ * K_ * D_HID_];
__device__ __align__(16) float g_o_pair[(size_t)B_ * K_ * D_OUT_];
__device__ __align__(16) float g_f1[(size_t)B_ * K_ * D_HID_];
__device__ __align__(16) float g_f2[(size_t)B_ * K_ * D_HID_];

// ==================== small kernels ====================
__global__ void init_kernel() {
    if (threadIdx.x < E_) { g_counts[threadIdx.x] = 0; g_cursor[threadIdx.x] = 0; }
    if (threadIdx.x == 0) g_bad = 0;
}

__global__ __launch_bounds__(256)
void prep_x(const float* __restrict__ x) {
    int i = blockIdx.x * 256 + threadIdx.x;
    float v = x[i];
    __nv_bfloat16 h = __float2bfloat16_rn(v);
    g_x_hi[i] = h;
    g_x_lo[i] = __float2bfloat16_rn(v - __bfloat162float(h));
}

__global__ __launch_bounds__(256)
void prep_w(const float* __restrict__ W, __nv_bfloat16* __restrict__ Whi,
            __nv_bfloat16* __restrict__ Wlo, int KD, int ND)
{
    __shared__ float t[32][33];
    const int e = blockIdx.z;
    const float* Wb = W + (size_t)e * KD * ND;
    __nv_bfloat16* Hh = Whi + (size_t)e * KD * ND;
    __nv_bfloat16* Hl = Wlo + (size_t)e * KD * ND;
    const int n0 = blockIdx.x * 32, k0 = blockIdx.y * 32;
    const int tx = threadIdx.x, ty = threadIdx.y;
    #pragma unroll
    for (int i = 0; i < 4; i++) {
        int kl = ty + i * 8;
        t[kl][tx] = Wb[(size_t)(k0 + kl) * ND + n0 + tx];
    }
    __syncthreads();
    #pragma unroll
    for (int i = 0; i < 4; i++) {
        int nl = ty + i * 8;
        float v = t[tx][nl];
        __nv_bfloat16 h = __float2bfloat16_rn(v);
        __nv_bfloat16 l = __float2bfloat16_rn(v - __bfloat162float(h));
        size_t o = (size_t)(n0 + nl) * KD + k0 + tx;
        Hh[o] = h; Hl[o] = l;
    }
}

__global__ __launch_bounds__(128)
void gate_kernel(const float* __restrict__ x,
                 const float* __restrict__ Wg1, const float* __restrict__ bg1,
                 const float* __restrict__ Wg2, const float* __restrict__ bg2,
                 const float* __restrict__ Wg3, const float* __restrict__ bg3,
                 float* __restrict__ out, long long out_sz)
{
    __shared__ __align__(16) float xs[8][D_IN_];
    __shared__ float s_g1[8][G_HID_];
    __shared__ float s_g2[8][G_HID_];
    __shared__ float s_lg[8][E_];

    const int tid = threadIdx.x;
    const int t0  = blockIdx.x * 8;

    const float4* xg  = reinterpret_cast<const float4*>(x + (size_t)t0 * D_IN_);
    float4*       xsv = reinterpret_cast<float4*>(&xs[0][0]);
    #pragma unroll
    for (int i = 0; i < (8 * D_IN_ / 4) / 128; i++)
        xsv[tid + i * 128] = xg[tid + i * 128];
    __syncthreads();

    float acc[8];
    #pragma unroll
    for (int t = 0; t < 8; t++) acc[t] = 0.f;
    for (int i = 0; i < D_IN_; i++) {
        float w = Wg1[i * G_HID_ + tid];
        #pragma unroll
        for (int t = 0; t < 8; t++) acc[t] = fmaf(xs[t][i], w, acc[t]);
    }
    {
        float b = bg1[tid];
        #pragma unroll
        for (int t = 0; t < 8; t++) s_g1[t][tid] = fmaxf(acc[t] + b, 0.f);
    }
    __syncthreads();

    #pragma unroll
    for (int t = 0; t < 8; t++) acc[t] = 0.f;
    for (int i = 0; i < G_HID_; i++) {
        float w = Wg2[i * G_HID_ + tid];
        #pragma unroll
        for (int t = 0; t < 8; t++) acc[t] = fmaf(s_g1[t][i], w, acc[t]);
    }
    {
        float b = bg2[tid];
        #pragma unroll
        for (int t = 0; t < 8; t++) s_g2[t][tid] = fmaxf(acc[t] + b, 0.f);
    }
    __syncthreads();

    if (tid < 64) {
        int t = tid >> 3, e = tid & 7;
        float a = bg3[e];
        for (int i = 0; i < G_HID_; i++)
            a = fmaf(s_g2[t][i], Wg3[i * E_ + e], a);
        s_lg[t][e] = a;
    }
    __syncthreads();

    if (tid < 8) {
        const int t   = tid;
        const int tok = t0 + t;
        float p[E_];
        float mx = s_lg[t][0];
        #pragma unroll
        for (int e = 1; e < E_; e++) mx = fmaxf(mx, s_lg[t][e]);
        float s = 0.f;
        #pragma unroll
        for (int e = 0; e < E_; e++) { p[e] = expf(s_lg[t][e] - mx); s += p[e]; }
        float inv = 1.f / s;
        float ent = 0.f;
        #pragma unroll
        for (int e = 0; e < E_; e++) { p[e] *= inv; ent -= p[e] * logf(p[e] + 1e-9f); }
        g_entropy[tok] = ent;

        int i1 = 0;
        #pragma unroll
        for (int e = 1; e < E_; e++) if (p[e] > p[i1]) i1 = e;
        int i2 = (i1 == 0) ? 1 : 0;
        #pragma unroll
        for (int e = 0; e < E_; e++) if (e != i1 && p[e] > p[i2]) i2 = e;

        float s1 = p[i1], s2 = p[i2];
        atomicAdd(&g_counts[i1], 1);
        atomicAdd(&g_counts[i2], 1);
        float denom = s1 + s2 + 1e-9f;
        g_tok_e[tok * 2 + 0] = i1;
        g_tok_e[tok * 2 + 1] = i2;
        g_tok_s[tok * 2 + 0] = s1 / denom;
        g_tok_s[tok * 2 + 1] = s2 / denom;

        long long idx_off = (long long)B_ * D_OUT_ + 1;
        long long sc_off  = idx_off + (long long)B_ * K_;
        if (out_sz >= sc_off + (long long)B_ * K_) {
            out[idx_off + tok * 2 + 0] = (float)i1;
            out[idx_off + tok * 2 + 1] = (float)i2;
            out[sc_off  + tok * 2 + 0] = s1;
            out[sc_off  + tok * 2 + 1] = s2;
        }
    }
}

__global__ void offsets_kernel() {
    if (threadIdx.x == 0 && blockIdx.x == 0) {
        int off = 0;
        for (int e = 0; e < E_; e++) {
            g_offsets[e] = off;
            g_cursor[e]  = off;
            off += g_counts[e];
        }
    }
}

__global__ void scatter_kernel() {
    int tok = blockIdx.x * blockDim.x + threadIdx.x;
    if (tok >= B_) return;
    #pragma unroll
    for (int k = 0; k < K_; k++) {
        int e = g_tok_e[tok * 2 + k];
        int pos = atomicAdd(&g_cursor[e], 1);
        g_pair_token[pos] = tok;
        g_tok_pos[tok * 2 + k] = pos;
    }
}

// ==================== HMMA expert GEMM (plain LDS, no swizzle/ldmatrix/cp.async) ====
// BM=128, BN=64, KC=32. Rows stored with 80B stride (40 bf16) => conflict-free LDS.
#define KC     32
#define A_ST   80
#define SA_HI  0
#define SA_LO  10240
#define SB_HI  20480
#define SB_LO  25600
#define SM_TOT 30720

template<int KDIM, int NDIM, int LAYER>
__global__ __launch_bounds__(256)
void moe_gemm(const float* __restrict__ bstack)
{
    __shared__ __align__(16) char sbuf[SM_TOT];

    const int e   = blockIdx.z;
    const int cnt = g_counts[e];
    const int m0  = blockIdx.x * 128;
    if (m0 >= cnt) return;
    const int off = g_offsets[e];
    const int n0  = blockIdx.y * 64;
    const int tid = threadIdx.x;

    const __nv_bfloat16* Ah = (LAYER == 1) ? g_x_hi : (LAYER == 2 ? g_h1_hi : g_h2_hi);
    const __nv_bfloat16* Al = (LAYER == 1) ? g_x_lo : (LAYER == 2 ? g_h1_lo : g_h2_lo);
    const __nv_bfloat16* Wh = (LAYER == 1) ? g_w1t_hi : (LAYER == 2 ? g_w2t_hi : g_w3t_hi);
    const __nv_bfloat16* Wl = (LAYER == 1) ? g_w1t_lo : (LAYER == 2 ? g_w2t_lo : g_w3t_lo);

    // 1536 16B-chunks per stage: Ahi[0,512) Alo[512,1024) Bhi[1024,1280) Blo[1280,1536)
    const __nv_bfloat16* gsrc[6];
    uint32_t soff[6];
    #pragma unroll
    for (int j = 0; j < 6; j++) {
        int idx = j * 256 + tid;
        if (idx < 1024) {
            int local = idx & 511;
            int r = local >> 2, c = local & 3;
            int mr = m0 + r; if (mr >= cnt) mr = cnt - 1;
            size_t base = (LAYER == 1) ? (size_t)g_pair_token[off + mr] * KDIM
                                       : (size_t)(off + mr) * KDIM;
            gsrc[j] = ((idx < 512) ? Ah : Al) + base + c * 8;
            soff[j] = ((idx < 512) ? SA_HI : SA_LO) + r * A_ST + c * 16;
        } else {
            int local = (idx - 1024) & 255;
            int r = local >> 2, c = local & 3;
            const __nv_bfloat16* W = (idx < 1280) ? Wh : Wl;
            gsrc[j] = W + (size_t)e * NDIM * KDIM + (size_t)(n0 + r) * KDIM + c * 8;
            soff[j] = ((idx < 1280) ? SB_HI : SB_LO) + r * A_ST + c * 16;
        }
    }

    const int wid = tid >> 5, lane = tid & 31;
    const int g   = lane >> 2, t4 = lane & 3;
    const int wm  = (wid & 3) * 32;    // warp m-origin (4 slots of 32)
    const int wn  = (wid >> 2) * 32;   // warp n-origin (2 slots of 32)

    float acc[2][4][4];
    #pragma unroll
    for (int i = 0; i < 2; i++)
        #pragma unroll
        for (int j = 0; j < 4; j++)
            #pragma unroll
            for (int k = 0; k < 4; k++) acc[i][j][k] = 0.f;

    uint4 v[6];
    #pragma unroll
    for (int j = 0; j < 6; j++) v[j] = *reinterpret_cast<const uint4*>(gsrc[j]);

    constexpr int NT = KDIM / KC;
    for (int t = 0; t < NT; t++) {
        __syncthreads();
        #pragma unroll
        for (int j = 0; j < 6; j++)
            *reinterpret_cast<uint4*>(sbuf + soff[j]) = v[j];
        __syncthreads();
        if (t + 1 < NT) {
            #pragma unroll
            for (int j = 0; j < 6; j++)
                v[j] = *reinterpret_cast<const uint4*>(gsrc[j] + (t + 1) * KC);
        }

        #pragma unroll
        for (int kk = 0; kk < 2; kk++) {
            uint32_t ah[2][4], al[2][4], bh[2][4], bl[2][4];
            #pragma unroll
            for (int mt = 0; mt < 2; mt++) {
                uint32_t b = (uint32_t)(wm + mt * 16 + g) * A_ST + kk * 32 + t4 * 4;
                ah[mt][0] = *reinterpret_cast<const uint32_t*>(sbuf + SA_HI + b);
                ah[mt][1] = *reinterpret_cast<const uint32_t*>(sbuf + SA_HI + b + 8 * A_ST);
                ah[mt][2] = *reinterpret_cast<const uint32_t*>(sbuf + SA_HI + b + 16);
                ah[mt][3] = *reinterpret_cast<const uint32_t*>(sbuf + SA_HI + b + 8 * A_ST + 16);
                al[mt][0] = *reinterpret_cast<const uint32_t*>(sbuf + SA_LO + b);
                al[mt][1] = *reinterpret_cast<const uint32_t*>(sbuf + SA_LO + b + 8 * A_ST);
                al[mt][2] = *reinterpret_cast<const uint32_t*>(sbuf + SA_LO + b + 16);
                al[mt][3] = *reinterpret_cast<const uint32_t*>(sbuf + SA_LO + b + 8 * A_ST + 16);
            }
            #pragma unroll
            for (int np = 0; np < 2; np++) {
                uint32_t b = (uint32_t)(wn + np * 16 + g) * A_ST + kk * 32 + t4 * 4;
                bh[np][0] = *reinterpret_cast<const uint32_t*>(sbuf + SB_HI + b);
                bh[np][1] = *reinterpret_cast<const uint32_t*>(sbuf + SB_HI + b + 16);
                bh[np][2] = *reinterpret_cast<const uint32_t*>(sbuf + SB_HI + b + 8 * A_ST);
                bh[np][3] = *reinterpret_cast<const uint32_t*>(sbuf + SB_HI + b + 8 * A_ST + 16);
                bl[np][0] = *reinterpret_cast<const uint32_t*>(sbuf + SB_LO + b);
                bl[np][1] = *reinterpret_cast<const uint32_t*>(sbuf + SB_LO + b + 16);
                bl[np][2] = *reinterpret_cast<const uint32_t*>(sbuf + SB_LO + b + 8 * A_ST);
                bl[np][3] = *reinterpret_cast<const uint32_t*>(sbuf + SB_LO + b + 8 * A_ST + 16);
            }
            #pragma unroll
            for (int mt = 0; mt < 2; mt++)
                #pragma unroll
                for (int np = 0; np < 2; np++) {
                    MMA_BF16(acc[mt][np * 2],     ah[mt][0], ah[mt][1], ah[mt][2], ah[mt][3], bh[np][0], bh[np][1]);
                    MMA_BF16(acc[mt][np * 2],     ah[mt][0], ah[mt][1], ah[mt][2], ah[mt][3], bl[np][0], bl[np][1]);
                    MMA_BF16(acc[mt][np * 2],     al[mt][0], al[mt][1], al[mt][2], al[mt][3], bh[np][0], bh[np][1]);
                    MMA_BF16(acc[mt][np * 2 + 1], ah[mt][0], ah[mt][1], ah[mt][2], ah[mt][3], bh[np][2], bh[np][3]);
                    MMA_BF16(acc[mt][np * 2 + 1], ah[mt][0], ah[mt][1], ah[mt][2], ah[mt][3], bl[np][2], bl[np][3]);
                    MMA_BF16(acc[mt][np * 2 + 1], al[mt][0], al[mt][1], al[mt][2], al[mt][3], bh[np][2], bh[np][3]);
                }
        }
    }

    // epilogue (C fragment: c0,c1 at row g, c2,c3 at row g+8; cols t4*2,+1)
    const int gid = lane >> 2, tig = lane & 3;
    __nv_bfloat16* Hh = (LAYER == 1) ? g_h1_hi : g_h2_hi;
    __nv_bfloat16* Hl = (LAYER == 1) ? g_h1_lo : g_h2_lo;

    #pragma unroll
    for (int mt = 0; mt < 2; mt++) {
        #pragma unroll
        for (int half = 0; half < 2; half++) {
            const int mr = m0 + wm + mt * 16 + gid + half * 8;
            if (mr >= cnt) continue;
            const size_t prow = (size_t)(off + mr);
            #pragma unroll
            for (int nt = 0; nt < 4; nt++) {
                const int col = n0 + wn + nt * 8 + tig * 2;
                float v0 = acc[mt][nt][half * 2 + 0] + bstack[(size_t)e * NDIM + col];
                float v1 = acc[mt][nt][half * 2 + 1] + bstack[(size_t)e * NDIM + col + 1];
                if (LAYER < 3) {
                    v0 = fmaxf(v0, 0.f);
                    v1 = fmaxf(v1, 0.f);
                    uint32_t hi, lo;
                    split2(v0, v1, hi, lo);
                    *reinterpret_cast<uint32_t*>(Hh + prow * NDIM + col) = hi;
                    *reinterpret_cast<uint32_t*>(Hl + prow * NDIM + col) = lo;
                } else {
                    float2 st; st.x = v0; st.y = v1;
                    *reinterpret_cast<float2*>(g_o_pair + prow * D_OUT_ + col) = st;
                }
            }
        }
    }
}

// ==================== verify: fp32 spot-check of HMMA chain ====================
__global__ __launch_bounds__(256)
void verify_kernel(const float* __restrict__ x,
                   const float* __restrict__ We1, const float* __restrict__ be1,
                   const float* __restrict__ We2, const float* __restrict__ be2,
                   const float* __restrict__ We3, const float* __restrict__ be3)
{
    __shared__ float a_in[D_HID_];
    __shared__ int s_bad;
    const int tid = threadIdx.x;
    if (tid == 0) s_bad = 0;
    __syncthreads();

    const int r = (blockIdx.x == 0) ? 0 : 101;
    int e = 0;
    for (int i = 0; i < E_; i++)
        if (g_offsets[i] <= r && r < g_offsets[i] + g_counts[i]) e = i;
    const int tok = g_pair_token[r];

    for (int i = tid; i < D_IN_; i += 256) a_in[i] = x[(size_t)tok * D_IN_ + i];
    __syncthreads();
    {
        const int j = tid;
        float s = be1[(size_t)e * D_HID_ + j];
        const float* w = We1 + (size_t)e * D_IN_ * D_HID_ + j;
        for (int k = 0; k < D_IN_; k++) s = fmaf(a_in[k], w[(size_t)k * D_HID_], s);
        s = fmaxf(s, 0.f);
        float got = __bfloat162float(g_h1_hi[(size_t)r * D_HID_ + j])
                  + __bfloat162float(g_h1_lo[(size_t)r * D_HID_ + j]);
        if (!(fabsf(got - s) <= 5e-3f * (fabsf(s) + 0.1f))) s_bad = 1;
    }
    __syncthreads();

    for (int i = tid; i < D_HID_; i += 256)
        a_in[i] = __bfloat162float(g_h1_hi[(size_t)r * D_HID_ + i])
                + __bfloat162float(g_h1_lo[(size_t)r * D_HID_ + i]);
    __syncthreads();
    {
        const int j = tid;
        float s = be2[(size_t)e * D_HID_ + j];
        const float* w = We2 + (size_t)e * D_HID_ * D_HID_ + j;
        for (int k = 0; k < D_HID_; k++) s = fmaf(a_in[k], w[(size_t)k * D_HID_], s);
        s = fmaxf(s, 0.f);
        float got = __bfloat162float(g_h2_hi[(size_t)r * D_HID_ + j])
                  + __bfloat162float(g_h2_lo[(size_t)r * D_HID_ + j]);
        if (!(fabsf(got - s) <= 5e-3f * (fabsf(s) + 0.1f))) s_bad = 1;
    }
    __syncthreads();

    for (int i = tid; i < D_HID_; i += 256)
        a_in[i] = __bfloat162float(g_h2_hi[(size_t)r * D_HID_ + i])
                + __bfloat162float(g_h2_lo[(size_t)r * D_HID_ + i]);
    __syncthreads();
    {
        const int j = tid;
        float s = be3[(size_t)e * D_OUT_ + j];
        const float* w = We3 + (size_t)e * D_HID_ * D_OUT_ + j;
        for (int k = 0; k < D_HID_; k++) s = fmaf(a_in[k], w[(size_t)k * D_OUT_], s);
        float got = g_o_pair[(size_t)r * D_OUT_ + j];
        if (!(fabsf(got - s) <= 5e-3f * (fabsf(s) + 0.1f))) s_bad = 1;
    }
    __syncthreads();
    if (tid == 0 && s_bad) atomicOr(&g_bad, 1);
}

// ==================== fp32 fallback GEMM (proven; runs only if g_bad) ====
#define BM 128
#define BN 128
#define BK 8

template<int KDIM, int NDIM, int EPI, int ASRC>
__global__ __launch_bounds__(256, 2)
void fb_gemm(const float* __restrict__ xptr,
             const float* __restrict__ Wstack,
             const float* __restrict__ bstack)
{
    if (g_bad == 0) return;

    const int e   = blockIdx.z;
    const int cnt = g_counts[e];
    const int m0  = blockIdx.y * BM;
    if (m0 >= cnt) return;
    const int off = g_offsets[e];
    const int n0  = blockIdx.x * BN;

    const float* __restrict__ Wb = Wstack + (size_t)e * KDIM * NDIM;
    const float* __restrict__ Abase =
        (ASRC == 0) ? xptr : (ASRC == 1 ? (const float*)g_f1 : (const float*)g_f2);
    float* __restrict__ Obase =
        (EPI == 0) ? (ASRC == 0 ? (float*)g_f1 : (float*)g_f2) : (float*)g_o_pair;

    __shared__ __align__(16) float As[2][BK][BM];
    __shared__ __align__(16) float Bs[2][BK][BN];

    const int tid   = threadIdx.x;
    const int a_row = tid >> 1;
    const int a_kq  = (tid & 1) << 2;
    const int b_k   = tid >> 5;
    const int b_n   = (tid & 31) << 2;

    int m  = m0 + a_row;
    int mm = (m < cnt) ? m : (cnt - 1);
    const float* __restrict__ Arow =
        (ASRC == 0) ? Abase + (size_t)g_pair_token[off + mm] * KDIM
                    : Abase + (size_t)(off + mm) * KDIM;

    const int tx = tid & 15;
    const int ty = tid >> 4;

    float acc[8][8];
    #pragma unroll
    for (int i = 0; i < 8; i++)
        #pragma unroll
        for (int j = 0; j < 8; j++) acc[i][j] = 0.f;

    {
        float4 av = *reinterpret_cast<const float4*>(Arow + a_kq);
        float4 bv = *reinterpret_cast<const float4*>(Wb + (size_t)b_k * NDIM + n0 + b_n);
        As[0][a_kq + 0][a_row] = av.x;
        As[0][a_kq + 1][a_row] = av.y;
        As[0][a_kq + 2][a_row] = av.z;
        As[0][a_kq + 3][a_row] = av.w;
        *reinterpret_cast<float4*>(&Bs[0][b_k][b_n]) = bv;
    }
    __syncthreads();

    const int ntiles = KDIM / BK;
    for (int t = 0; t < ntiles; ++t) {
        const int cur = t & 1;
        const int nxt = cur ^ 1;
        float4 an, bn;
        if (t + 1 < ntiles) {
            const int k0 = (t + 1) * BK;
            an = *reinterpret_cast<const float4*>(Arow + k0 + a_kq);
            bn = *reinterpret_cast<const float4*>(Wb + (size_t)(k0 + b_k) * NDIM + n0 + b_n);
        }
        #pragma unroll
        for (int kk = 0; kk < BK; kk++) {
            float ar[8], br[8];
            *reinterpret_cast<float4*>(&ar[0]) = *reinterpret_cast<const float4*>(&As[cur][kk][ty * 8]);
            *reinterpret_cast<float4*>(&ar[4]) = *reinterpret_cast<const float4*>(&As[cur][kk][ty * 8 + 4]);
            *reinterpret_cast<float4*>(&br[0]) = *reinterpret_cast<const float4*>(&Bs[cur][kk][tx * 8]);
            *reinterpret_cast<float4*>(&br[4]) = *reinterpret_cast<const float4*>(&Bs[cur][kk][tx * 8 + 4]);
            #pragma unroll
            for (int i = 0; i < 8; i++)
                #pragma unroll
                for (int j = 0; j < 8; j++)
                    acc[i][j] = fmaf(ar[i], br[j], acc[i][j]);
        }
        if (t + 1 < ntiles) {
            As[nxt][a_kq + 0][a_row] = an.x;
            As[nxt][a_kq + 1][a_row] = an.y;
            As[nxt][a_kq + 2][a_row] = an.z;
            As[nxt][a_kq + 3][a_row] = an.w;
            *reinterpret_cast<float4*>(&Bs[nxt][b_k][b_n]) = bn;
        }
        __syncthreads();
    }

    const int col0 = n0 + tx * 8;
    float bias[8];
    #pragma unroll
    for (int j = 0; j < 8; j++) bias[j] = bstack[(size_t)e * NDIM + col0 + j];

    #pragma unroll
    for (int i = 0; i < 8; i++) {
        int mr = m0 + ty * 8 + i;
        if (mr >= cnt) continue;
        float* orow = Obase + (size_t)(off + mr) * NDIM + col0;
        #pragma unroll
        for (int j = 0; j < 8; j++) {
            float v = acc[i][j] + bias[j];
            orow[j] = (EPI == 0) ? fmaxf(v, 0.f) : v;
        }
    }
}

// ==================== combine + finalize ====================
__global__ __launch_bounds__(256)
void combine_kernel(float* __restrict__ out)
{
    int i = blockIdx.x * 256 + threadIdx.x;
    int tok = i >> 10, c = i & 1023;
    float v = g_tok_s[tok * 2 + 0] * g_o_pair[(size_t)g_tok_pos[tok * 2 + 0] * D_OUT_ + c]
            + g_tok_s[tok * 2 + 1] * g_o_pair[(size_t)g_tok_pos[tok * 2 + 1] * D_OUT_ + c];
    out[i] = v;
}

__global__ __launch_bounds__(1024)
void finalize_kernel(float* __restrict__ out, long long out_sz)
{
    __shared__ float red[1024];
    const int tid = threadIdx.x;
    float s = 0.f;
    for (int i = tid; i < B_; i += 1024) s += g_entropy[i];
    red[tid] = s;
    __syncthreads();
    for (int st = 512; st > 0; st >>= 1) {
        if (tid < st) red[tid] += red[tid + st];
        __syncthreads();
    }
    if (tid == 0) {
        float ent_mean = red[0] / (float)B_;
        float load[E_];
        float mean = 0.f;
        for (int e = 0; e < E_; e++) {
            load[e] = (float)g_counts[e] / ((float)B_ + 1e-9f);
            mean += load[e];
        }
        mean /= (float)E_;
        float var = 0.f;
        for (int e = 0; e < E_; e++) {
            float d = load[e] - mean;
            var += d * d;
        }
        var /= (float)(E_ - 1);
        float aux = 5.0f * var + 0.1f * ent_mean;
        long long aux_off = (long long)B_ * D_OUT_;
        if (out_sz > aux_off) out[aux_off] = aux;
    }
}

// ==================== launch ====================
extern "C" void kernel_launch(void* const* d_in, const int* in_sizes, int n_in,
                              void* d_out, int out_size)
{
    const float* x   = (const float*)d_in[0];
    const float* We1 = (const float*)d_in[1];
    const float* be1 = (const float*)d_in[2];
    const float* We2 = (const float*)d_in[3];
    const float* be2 = (const float*)d_in[4];
    const float* We3 = (const float*)d_in[5];
    const float* be3 = (const float*)d_in[6];
    const float* Wg1 = (const float*)d_in[7];
    const float* bg1 = (const float*)d_in[8];
    const float* Wg2 = (const float*)d_in[9];
    const float* bg2 = (const float*)d_in[10];
    const float* Wg3 = (const float*)d_in[11];
    const float* bg3 = (const float*)d_in[12];
    float* out = (float*)d_out;
    long long out_sz = (long long)out_size;

    init_kernel<<<1, 32>>>();
    gate_kernel<<<B_ / 8, 128>>>(x, Wg1, bg1, Wg2, bg2, Wg3, bg3, out, out_sz);
    offsets_kernel<<<1, 32>>>();
    scatter_kernel<<<(B_ + 255) / 256, 256>>>();

    prep_x<<<(B_ * D_IN_) / 256, 256>>>(x);
    prep_w<<<dim3(D_HID_ / 32, D_IN_  / 32, E_), dim3(32, 8)>>>(We1, g_w1t_hi, g_w1t_lo, D_IN_,  D_HID_);
    prep_w<<<dim3(D_HID_ / 32, D_HID_ / 32, E_), dim3(32, 8)>>>(We2, g_w2t_hi, g_w2t_lo, D_HID_, D_HID_);
    prep_w<<<dim3(D_OUT_ / 32, D_HID_ / 32, E_), dim3(32, 8)>>>(We3, g_w3t_hi, g_w3t_lo, D_HID_, D_OUT_);

    const int max_mt = B_ / 128;
    moe_gemm<D_IN_,  D_HID_, 1><<<dim3(max_mt, D_HID_ / 64, E_), 256>>>(be1);
    moe_gemm<D_HID_, D_HID_, 2><<<dim3(max_mt, D_HID_ / 64, E_), 256>>>(be2);
    moe_gemm<D_HID_, D_OUT_, 3><<<dim3(max_mt, D_OUT_ / 64, E_), 256>>>(be3);

    verify_kernel<<<2, 256>>>(x, We1, be1, We2, be2, We3, be3);

    fb_gemm<D_IN_,  D_HID_, 0, 0><<<dim3(D_HID_ / BN, max_mt, E_), 256>>>(x, We1, be1);
    fb_gemm<D_HID_, D_HID_, 0, 1><<<dim3(D_HID_ / BN, max_mt, E_), 256>>>(x, We2, be2);
    fb_gemm<D_HID_, D_OUT_, 2, 2><<<dim3(D_OUT_ / BN, max_mt, E_), 256>>>(x, We3, be3);

    combine_kernel<<<(B_ * D_OUT_) / 256, 256>>>(out);
    finalize_kernel<<<1, 1024>>>(out, out_sz);
}